// round 9
// baseline (speedup 1.0000x reference)
#include <cuda_runtime.h>
#include <cuda_fp16.h>

#define DM 64
#define MAXN 131072
#define MAXE 2097152

// ---------------- scratch (device globals) ----------------------------------
// g_cnt layout: [0,MAXN) = ecnt, [MAXN,2*MAXN) = fill cursors, [2*MAXN] = scan flag
__device__ int    g_cnt[2 * MAXN + 4];
__device__ int    g_rowptr[MAXN + 1];
__device__ int    g_bsum[256];
__device__ float  g_dis[MAXN];
__device__ int    g_csrc[MAXE];
__device__ __half g_bufA[(size_t)MAXN * DM];
__device__ __half g_bufB[(size_t)MAXN * DM];
__device__ float  g_W012[DM * DM];    // W0 @ W1 @ W2
__device__ float  g_bv0[DM];          // b0 @ W1 @ W2
__device__ float  g_bv1[DM];          // b1 @ W2

// ---------------- preprocessing ----------------------------------------------
__global__ void k_count(const int* __restrict__ dst, int E) {
    int i = blockIdx.x * blockDim.x + threadIdx.x;
    if (i < E) atomicAdd(&g_cnt[dst[i]], 1);
}

// single-kernel exclusive scan of g_cnt[0..n) -> g_rowptr, plus dis = rsqrt(deg+1).
__global__ __launch_bounds__(256) void k_scanf(int n, int nb) {
    __shared__ int wsum[8];
    __shared__ int red[8];
    __shared__ int sbase;
    int t = threadIdx.x;
    int blk = blockIdx.x;
    int lane = t & 31, wid = t >> 5;
    int base = blk * 1024 + t * 4;

    int4 v = make_int4(0, 0, 0, 0);
    if (base + 3 < n) v = *(const int4*)(g_cnt + base);
    else {
        if (base     < n) v.x = g_cnt[base];
        if (base + 1 < n) v.y = g_cnt[base + 1];
        if (base + 2 < n) v.z = g_cnt[base + 2];
    }
    int s = v.x + v.y + v.z + v.w;

    int sc = s;
#pragma unroll
    for (int o = 1; o < 32; o <<= 1) {
        int u = __shfl_up_sync(0xffffffffu, sc, o);
        if (lane >= o) sc += u;
    }
    if (lane == 31) wsum[wid] = sc;
    __syncthreads();
    if (t < 8) {
        int x = wsum[t];
#pragma unroll
        for (int o = 1; o < 8; o <<= 1) {
            int u = __shfl_up_sync(0xffu, x, o);
            if (t >= o) x += u;
        }
        wsum[t] = x;
    }
    __syncthreads();
    int thr_incl = sc + (wid ? wsum[wid - 1] : 0);
    int block_total = wsum[7];

    volatile int* flag = (volatile int*)&g_cnt[2 * MAXN];
    if (t == 0) {
        g_bsum[blk] = block_total;
        __threadfence();
        atomicAdd((int*)&g_cnt[2 * MAXN], 1);
        while (*flag < nb) __nanosleep(64);
    }
    __syncthreads();

    int pv = (t < blk) ? __ldcg(&g_bsum[t]) : 0;
#pragma unroll
    for (int o = 16; o > 0; o >>= 1) pv += __shfl_down_sync(0xffffffffu, pv, o);
    if (lane == 0) red[wid] = pv;
    __syncthreads();
    if (t == 0) {
        int x = 0;
#pragma unroll
        for (int j = 0; j < 8; j++) x += red[j];
        sbase = x;
    }
    __syncthreads();

    int start = sbase + thr_incl - s;
    if (base + 3 < n) {
        int4 rp;
        rp.x = start;
        rp.y = rp.x + v.x;
        rp.z = rp.y + v.y;
        rp.w = rp.z + v.z;
        *(int4*)(g_rowptr + base) = rp;
        float4 dv;
        dv.x = rsqrtf((float)(v.x + 1));
        dv.y = rsqrtf((float)(v.y + 1));
        dv.z = rsqrtf((float)(v.z + 1));
        dv.w = rsqrtf((float)(v.w + 1));
        *(float4*)(g_dis + base) = dv;
        if (base + 4 == n) g_rowptr[n] = rp.w + v.w;
    } else {
        int e = start;
        int vv[4] = { v.x, v.y, v.z, v.w };
        for (int j = 0; j < 4; j++) {
            int i = base + j;
            if (i < n) {
                g_rowptr[i] = e;
                g_dis[i] = rsqrtf((float)(vv[j] + 1));
                e += vv[j];
                if (i == n - 1) g_rowptr[n] = e;
            }
        }
    }
}

__global__ void k_fill(const int* __restrict__ src, const int* __restrict__ dst, int E) {
    int e = blockIdx.x * blockDim.x + threadIdx.x;
    if (e < E) {
        int d = dst[e];
        int pos = g_rowptr[d] + atomicAdd(&g_cnt[MAXN + d], 1);
        g_csrc[pos] = src[e];
    }
}

// ---------------- fused weight products: single block ---------------------------
// W12 = W1@W2 (smem only), bv1 = b1@W2, W012 = W0@W12, bv0 = b0@W12
__global__ __launch_bounds__(256) void k_wfuse(const float* __restrict__ W0,
                                               const float* __restrict__ b0,
                                               const float* __restrict__ W1,
                                               const float* __restrict__ b1,
                                               const float* __restrict__ W2) {
    __shared__ float sA[DM][DM + 1];   // W1, then W0
    __shared__ float sB[DM][DM + 1];   // W2
    __shared__ float sC[DM][DM + 1];   // W12
    int t = threadIdx.x;

    for (int i = t; i < DM * DM; i += 256) {
        sA[i >> 6][i & 63] = W1[i];
        sB[i >> 6][i & 63] = W2[i];
    }
    __syncthreads();

    // W12 = W1@W2 -> sC ; bv1 = b1@W2
#pragma unroll
    for (int k = 0; k < 16; k++) {
        int idx = t + k * 256;
        int r = idx >> 6, c = idx & 63;
        float acc = 0.f;
#pragma unroll
        for (int m = 0; m < DM; m++) acc += sA[r][m] * sB[m][c];
        sC[r][c] = acc;
    }
    if (t < DM) {
        float acc = 0.f;
#pragma unroll
        for (int m = 0; m < DM; m++) acc += b1[m] * sB[m][t];
        g_bv1[t] = acc;
    }
    __syncthreads();

    // overwrite sA with W0
    for (int i = t; i < DM * DM; i += 256) sA[i >> 6][i & 63] = W0[i];
    __syncthreads();

    // W012 = W0@W12 -> global ; bv0 = b0@W12
#pragma unroll
    for (int k = 0; k < 16; k++) {
        int idx = t + k * 256;
        int r = idx >> 6, c = idx & 63;
        float acc = 0.f;
#pragma unroll
        for (int m = 0; m < DM; m++) acc += sA[r][m] * sC[m][c];
        g_W012[idx] = acc;
    }
    if (t < DM) {
        float acc = 0.f;
#pragma unroll
        for (int m = 0; m < DM; m++) acc += b0[m] * sC[m][t];
        g_bv0[t] = acc;
    }
}

// ---------------- GEMM: bufA = fp16( (X @ W012) * dis[row] ), f32x2 FFMA --------
#define FFMA2(acc, a, b) \
    asm("fma.rn.f32x2 %0, %1, %2, %0;" : "+l"(acc) : "l"(a), "l"(b))

__global__ __launch_bounds__(256) void k_gemm(const float* __restrict__ X, int n) {
    __shared__ float xs[64][72];
    __shared__ float ws[64][72];
    int tid = threadIdx.x;
    int row0 = blockIdx.x * 64;

#pragma unroll
    for (int k = 0; k < 4; k++) {
        int idx = tid + k * 256;
        int r = idx >> 4;
        int c = (idx & 15) << 2;
        *(float4*)&ws[r][c] = *(const float4*)(g_W012 + r * DM + c);
        int gr = row0 + r;
        float4 xv = make_float4(0.f, 0.f, 0.f, 0.f);
        if (gr < n) xv = *(const float4*)(X + (size_t)gr * DM + c);
        *(float4*)&xs[r][c] = xv;
    }
    __syncthreads();

    int tx = tid & 15, ty = tid >> 4;
    unsigned long long acc[4][2] = {};
#pragma unroll
    for (int k2 = 0; k2 < 64; k2++) {
        ulonglong2 wv = *(ulonglong2*)&ws[k2][tx * 4];
#pragma unroll
        for (int i = 0; i < 4; i++) {
            unsigned int au = __float_as_uint(xs[ty * 4 + i][k2]);
            unsigned long long ap;
            asm("mov.b64 %0, {%1, %1};" : "=l"(ap) : "r"(au));
            FFMA2(acc[i][0], ap, wv.x);
            FFMA2(acc[i][1], ap, wv.y);
        }
    }

#pragma unroll
    for (int i = 0; i < 4; i++) {
        int r = row0 + ty * 4 + i;
        if (r < n) {
            float s = g_dis[r];
            float2 p0 = *(float2*)&acc[i][0];
            float2 p1 = *(float2*)&acc[i][1];
            __half2* orow = (__half2*)(g_bufA + (size_t)r * DM);
            orow[tx * 2 + 0] = __floats2half2_rn(p0.x * s, p0.y * s);
            orow[tx * 2 + 1] = __floats2half2_rn(p1.x * s, p1.y * s);
        }
    }
}

// ---------------- S-apply pass (warp per node, fp16 rows, fp32 accum) -----------
// Gin rows pre-scaled by dis[src]. acc = self + neighbors.
// intermediate: Gout(fp16) = fp16( dis^2*acc + dis*c )
// final:        OUT (fp32) = dis*acc + c
__global__ __launch_bounds__(256) void k_agg(const __half* __restrict__ Gin,
                                             const float* __restrict__ cvec,
                                             __half* __restrict__ Gout,
                                             float* __restrict__ OUT,
                                             int n, int fin) {
    int w    = (blockIdx.x * blockDim.x + threadIdx.x) >> 5;
    int lane = threadIdx.x & 31;
    if (w >= n) return;

    int p   = g_rowptr[w];
    int end = g_rowptr[w + 1];
    const __half2* G2 = (const __half2*)Gin;
    size_t selfoff = (size_t)w * 32 + lane;

    float2 acc = __half22float2(G2[selfoff]);
    for (; p + 3 < end; p += 4) {
        int s0 = g_csrc[p], s1 = g_csrc[p + 1], s2 = g_csrc[p + 2], s3 = g_csrc[p + 3];
        float2 v0 = __half22float2(G2[(size_t)s0 * 32 + lane]);
        float2 v1 = __half22float2(G2[(size_t)s1 * 32 + lane]);
        float2 v2 = __half22float2(G2[(size_t)s2 * 32 + lane]);
        float2 v3 = __half22float2(G2[(size_t)s3 * 32 + lane]);
        acc.x += v0.x + v1.x + v2.x + v3.x;
        acc.y += v0.y + v1.y + v2.y + v3.y;
    }
    for (; p < end; p++) {
        float2 v = __half22float2(G2[(size_t)g_csrc[p] * 32 + lane]);
        acc.x += v.x; acc.y += v.y;
    }

    float dv = g_dis[w];
    float2 c = ((const float2*)cvec)[lane];
    if (fin) {
        float2 o;
        o.x = dv * acc.x + c.x;
        o.y = dv * acc.y + c.y;
        ((float2*)OUT)[selfoff] = o;
    } else {
        float f = dv * dv;
        ((__half2*)Gout)[selfoff] = __floats2half2_rn(f * acc.x + dv * c.x,
                                                      f * acc.y + dv * c.y);
    }
}

// ---------------- launch --------------------------------------------------------
extern "C" void kernel_launch(void* const* d_in, const int* in_sizes, int n_in,
                              void* d_out, int out_size) {
    const float* x  = (const float*)d_in[0];
    const int*   ei = (const int*)d_in[1];
    int n = in_sizes[0] / DM;
    int E = in_sizes[1] / 2;
    const int* src = ei;
    const int* dst = ei + E;

    const float* W0 = (const float*)d_in[2];
    const float* b0 = (const float*)d_in[3];
    const float* W1 = (const float*)d_in[4];
    const float* b1 = (const float*)d_in[5];
    const float* W2 = (const float*)d_in[6];
    const float* b2 = (const float*)d_in[7];

    void *cnt_p = nullptr, *bv0_p = nullptr, *bv1_p = nullptr;
    void *bufA_p = nullptr, *bufB_p = nullptr;
    cudaGetSymbolAddress(&cnt_p, g_cnt);
    cudaGetSymbolAddress(&bv0_p, g_bv0);
    cudaGetSymbolAddress(&bv1_p, g_bv1);
    cudaGetSymbolAddress(&bufA_p, g_bufA);
    cudaGetSymbolAddress(&bufB_p, g_bufB);

    int nb = (n + 1023) / 1024;

    cudaMemsetAsync(cnt_p, 0, (size_t)(2 * MAXN + 4) * sizeof(int));

    k_wfuse<<<1, 256>>>(W0, b0, W1, b1, W2);
    k_count<<<(E + 255) / 256, 256>>>(dst, E);
    k_scanf<<<nb, 256>>>(n, nb);
    k_fill <<<(E + 255) / 256, 256>>>(src, dst, E);

    int gemm_blocks = (n + 63) / 64;
    int agg_blocks  = (n + 7) / 8;

    k_gemm<<<gemm_blocks, 256>>>(x, n);  // -> bufA fp16 (pre-scaled by dis)
    k_agg <<<agg_blocks, 256>>>((const __half*)bufA_p, (const float*)bv0_p,
                                (__half*)bufB_p, nullptr, n, 0);
    k_agg <<<agg_blocks, 256>>>((const __half*)bufB_p, (const float*)bv1_p,
                                (__half*)bufA_p, nullptr, n, 0);
    k_agg <<<agg_blocks, 256>>>((const __half*)bufA_p, b2,
                                nullptr, (float*)d_out, n, 1);
}

// round 12
// speedup vs baseline: 1.1489x; 1.1489x over previous
#include <cuda_runtime.h>

#define DM 64
#define MAXN 131072
#define MAXE 2097152

// ---------------- scratch (device globals) ----------------------------------
// g_cnt layout: [0,MAXN) = ecnt, [MAXN,2*MAXN) = fill cursors, [2*MAXN] = scan flag
__device__ int    g_cnt[2 * MAXN + 4];
__device__ int    g_rowptr[MAXN + 1];
__device__ int    g_bsum[256];
__device__ float  g_dis[MAXN];
__device__ int    g_csrc[MAXE];
__device__ float  g_bufA[(size_t)MAXN * DM];
__device__ float  g_bufB[(size_t)MAXN * DM];
__device__ float  g_W012[DM * DM];    // W0 @ W1 @ W2
__device__ float  g_bv0[DM];          // b0 @ W1 @ W2
__device__ float  g_bv1[DM];          // b1 @ W2

// ---------------- preprocessing ----------------------------------------------
// 4 edges per thread for MLP
__global__ __launch_bounds__(256) void k_count(const int* __restrict__ dst, int E) {
    int base = (blockIdx.x * blockDim.x + threadIdx.x) * 4;
    if (base + 3 < E) {
        int4 d = *(const int4*)(dst + base);
        atomicAdd(&g_cnt[d.x], 1);
        atomicAdd(&g_cnt[d.y], 1);
        atomicAdd(&g_cnt[d.z], 1);
        atomicAdd(&g_cnt[d.w], 1);
    } else {
        for (int j = 0; j < 4; j++)
            if (base + j < E) atomicAdd(&g_cnt[dst[base + j]], 1);
    }
}

// single-kernel exclusive scan of g_cnt[0..n) -> g_rowptr, plus dis = rsqrt(deg+1).
__global__ __launch_bounds__(256) void k_scanf(int n, int nb) {
    __shared__ int wsum[8];
    __shared__ int red[8];
    __shared__ int sbase;
    int t = threadIdx.x;
    int blk = blockIdx.x;
    int lane = t & 31, wid = t >> 5;
    int base = blk * 1024 + t * 4;

    int4 v = make_int4(0, 0, 0, 0);
    if (base + 3 < n) v = *(const int4*)(g_cnt + base);
    else {
        if (base     < n) v.x = g_cnt[base];
        if (base + 1 < n) v.y = g_cnt[base + 1];
        if (base + 2 < n) v.z = g_cnt[base + 2];
    }
    int s = v.x + v.y + v.z + v.w;

    int sc = s;
#pragma unroll
    for (int o = 1; o < 32; o <<= 1) {
        int u = __shfl_up_sync(0xffffffffu, sc, o);
        if (lane >= o) sc += u;
    }
    if (lane == 31) wsum[wid] = sc;
    __syncthreads();
    if (t < 8) {
        int x = wsum[t];
#pragma unroll
        for (int o = 1; o < 8; o <<= 1) {
            int u = __shfl_up_sync(0xffu, x, o);
            if (t >= o) x += u;
        }
        wsum[t] = x;
    }
    __syncthreads();
    int thr_incl = sc + (wid ? wsum[wid - 1] : 0);
    int block_total = wsum[7];

    volatile int* flag = (volatile int*)&g_cnt[2 * MAXN];
    if (t == 0) {
        g_bsum[blk] = block_total;
        __threadfence();
        atomicAdd((int*)&g_cnt[2 * MAXN], 1);
        while (*flag < nb) __nanosleep(64);
    }
    __syncthreads();

    int pv = (t < blk) ? __ldcg(&g_bsum[t]) : 0;
#pragma unroll
    for (int o = 16; o > 0; o >>= 1) pv += __shfl_down_sync(0xffffffffu, pv, o);
    if (lane == 0) red[wid] = pv;
    __syncthreads();
    if (t == 0) {
        int x = 0;
#pragma unroll
        for (int j = 0; j < 8; j++) x += red[j];
        sbase = x;
    }
    __syncthreads();

    int start = sbase + thr_incl - s;
    if (base + 3 < n) {
        int4 rp;
        rp.x = start;
        rp.y = rp.x + v.x;
        rp.z = rp.y + v.y;
        rp.w = rp.z + v.z;
        *(int4*)(g_rowptr + base) = rp;
        float4 dv;
        dv.x = rsqrtf((float)(v.x + 1));
        dv.y = rsqrtf((float)(v.y + 1));
        dv.z = rsqrtf((float)(v.z + 1));
        dv.w = rsqrtf((float)(v.w + 1));
        *(float4*)(g_dis + base) = dv;
        if (base + 4 == n) g_rowptr[n] = rp.w + v.w;
    } else {
        int e = start;
        int vv[4] = { v.x, v.y, v.z, v.w };
        for (int j = 0; j < 4; j++) {
            int i = base + j;
            if (i < n) {
                g_rowptr[i] = e;
                g_dis[i] = rsqrtf((float)(vv[j] + 1));
                e += vv[j];
                if (i == n - 1) g_rowptr[n] = e;
            }
        }
    }
}

// 4 edges per thread for MLP
__global__ __launch_bounds__(256) void k_fill(const int* __restrict__ src,
                                              const int* __restrict__ dst, int E) {
    int base = (blockIdx.x * blockDim.x + threadIdx.x) * 4;
    if (base + 3 < E) {
        int4 d = *(const int4*)(dst + base);
        int4 s = *(const int4*)(src + base);
        int p0 = g_rowptr[d.x] + atomicAdd(&g_cnt[MAXN + d.x], 1);
        int p1 = g_rowptr[d.y] + atomicAdd(&g_cnt[MAXN + d.y], 1);
        int p2 = g_rowptr[d.z] + atomicAdd(&g_cnt[MAXN + d.z], 1);
        int p3 = g_rowptr[d.w] + atomicAdd(&g_cnt[MAXN + d.w], 1);
        g_csrc[p0] = s.x;
        g_csrc[p1] = s.y;
        g_csrc[p2] = s.z;
        g_csrc[p3] = s.w;
    } else {
        for (int j = 0; j < 4; j++) {
            if (base + j < E) {
                int d = dst[base + j];
                int pos = g_rowptr[d] + atomicAdd(&g_cnt[MAXN + d], 1);
                g_csrc[pos] = src[base + j];
            }
        }
    }
}

// ---------------- fused weight products: single block ---------------------------
__global__ __launch_bounds__(256) void k_wfuse(const float* __restrict__ W0,
                                               const float* __restrict__ b0,
                                               const float* __restrict__ W1,
                                               const float* __restrict__ b1,
                                               const float* __restrict__ W2) {
    __shared__ float sA[DM][DM + 1];
    __shared__ float sB[DM][DM + 1];
    __shared__ float sC[DM][DM + 1];
    int t = threadIdx.x;

    for (int i = t; i < DM * DM; i += 256) {
        sA[i >> 6][i & 63] = W1[i];
        sB[i >> 6][i & 63] = W2[i];
    }
    __syncthreads();

#pragma unroll
    for (int k = 0; k < 16; k++) {
        int idx = t + k * 256;
        int r = idx >> 6, c = idx & 63;
        float acc = 0.f;
#pragma unroll
        for (int m = 0; m < DM; m++) acc += sA[r][m] * sB[m][c];
        sC[r][c] = acc;
    }
    if (t < DM) {
        float acc = 0.f;
#pragma unroll
        for (int m = 0; m < DM; m++) acc += b1[m] * sB[m][t];
        g_bv1[t] = acc;
    }
    __syncthreads();

    for (int i = t; i < DM * DM; i += 256) sA[i >> 6][i & 63] = W0[i];
    __syncthreads();

#pragma unroll
    for (int k = 0; k < 16; k++) {
        int idx = t + k * 256;
        int r = idx >> 6, c = idx & 63;
        float acc = 0.f;
#pragma unroll
        for (int m = 0; m < DM; m++) acc += sA[r][m] * sC[m][c];
        g_W012[idx] = acc;
    }
    if (t < DM) {
        float acc = 0.f;
#pragma unroll
        for (int m = 0; m < DM; m++) acc += b0[m] * sC[m][t];
        g_bv0[t] = acc;
    }
}

// ---------------- GEMM: bufA = (X @ W012) * dis[row], fp32, f32x2 FFMA ---------
#define FFMA2(acc, a, b) \
    asm("fma.rn.f32x2 %0, %1, %2, %0;" : "+l"(acc) : "l"(a), "l"(b))

__global__ __launch_bounds__(256) void k_gemm(const float* __restrict__ X, int n) {
    __shared__ float xs[64][72];
    __shared__ float ws[64][72];
    int tid = threadIdx.x;
    int row0 = blockIdx.x * 64;

#pragma unroll
    for (int k = 0; k < 4; k++) {
        int idx = tid + k * 256;
        int r = idx >> 4;
        int c = (idx & 15) << 2;
        *(float4*)&ws[r][c] = *(const float4*)(g_W012 + r * DM + c);
        int gr = row0 + r;
        float4 xv = make_float4(0.f, 0.f, 0.f, 0.f);
        if (gr < n) xv = *(const float4*)(X + (size_t)gr * DM + c);
        *(float4*)&xs[r][c] = xv;
    }
    __syncthreads();

    int tx = tid & 15, ty = tid >> 4;
    unsigned long long acc[4][2] = {};
#pragma unroll
    for (int k2 = 0; k2 < 64; k2++) {
        ulonglong2 wv = *(ulonglong2*)&ws[k2][tx * 4];
#pragma unroll
        for (int i = 0; i < 4; i++) {
            unsigned int au = __float_as_uint(xs[ty * 4 + i][k2]);
            unsigned long long ap;
            asm("mov.b64 %0, {%1, %1};" : "=l"(ap) : "r"(au));
            FFMA2(acc[i][0], ap, wv.x);
            FFMA2(acc[i][1], ap, wv.y);
        }
    }

#pragma unroll
    for (int i = 0; i < 4; i++) {
        int r = row0 + ty * 4 + i;
        if (r < n) {
            float s = g_dis[r];
            float2 p0 = *(float2*)&acc[i][0];
            float2 p1 = *(float2*)&acc[i][1];
            float4 o = make_float4(p0.x * s, p0.y * s, p1.x * s, p1.y * s);
            *(float4*)(g_bufA + (size_t)r * DM + tx * 4) = o;
        }
    }
}

// ---------------- S-apply pass (warp per node, fp32) -----------------------------
__global__ __launch_bounds__(256) void k_agg(const float* __restrict__ Gin,
                                             const float* __restrict__ cvec,
                                             float* __restrict__ Gout,
                                             int n, int fin) {
    int w    = (blockIdx.x * blockDim.x + threadIdx.x) >> 5;
    int lane = threadIdx.x & 31;
    if (w >= n) return;

    int p   = g_rowptr[w];
    int end = g_rowptr[w + 1];
    const float2* G2 = (const float2*)Gin;
    size_t selfoff = (size_t)w * 32 + lane;

    float2 acc = G2[selfoff];
    // unroll 8: 8 independent gathers in flight
    for (; p + 7 < end; p += 8) {
        int s0 = g_csrc[p],     s1 = g_csrc[p + 1], s2 = g_csrc[p + 2], s3 = g_csrc[p + 3];
        int s4 = g_csrc[p + 4], s5 = g_csrc[p + 5], s6 = g_csrc[p + 6], s7 = g_csrc[p + 7];
        float2 v0 = G2[(size_t)s0 * 32 + lane];
        float2 v1 = G2[(size_t)s1 * 32 + lane];
        float2 v2 = G2[(size_t)s2 * 32 + lane];
        float2 v3 = G2[(size_t)s3 * 32 + lane];
        float2 v4 = G2[(size_t)s4 * 32 + lane];
        float2 v5 = G2[(size_t)s5 * 32 + lane];
        float2 v6 = G2[(size_t)s6 * 32 + lane];
        float2 v7 = G2[(size_t)s7 * 32 + lane];
        acc.x += ((v0.x + v1.x) + (v2.x + v3.x)) + ((v4.x + v5.x) + (v6.x + v7.x));
        acc.y += ((v0.y + v1.y) + (v2.y + v3.y)) + ((v4.y + v5.y) + (v6.y + v7.y));
    }
    for (; p + 3 < end; p += 4) {
        int s0 = g_csrc[p], s1 = g_csrc[p + 1], s2 = g_csrc[p + 2], s3 = g_csrc[p + 3];
        float2 v0 = G2[(size_t)s0 * 32 + lane];
        float2 v1 = G2[(size_t)s1 * 32 + lane];
        float2 v2 = G2[(size_t)s2 * 32 + lane];
        float2 v3 = G2[(size_t)s3 * 32 + lane];
        acc.x += (v0.x + v1.x) + (v2.x + v3.x);
        acc.y += (v0.y + v1.y) + (v2.y + v3.y);
    }
    for (; p < end; p++) {
        float2 v = G2[(size_t)g_csrc[p] * 32 + lane];
        acc.x += v.x; acc.y += v.y;
    }

    float dv = g_dis[w];
    float2 c = ((const float2*)cvec)[lane];
    float2 o;
    if (fin) {
        o.x = dv * acc.x + c.x;
        o.y = dv * acc.y + c.y;
    } else {
        float f = dv * dv;
        o.x = f * acc.x + dv * c.x;
        o.y = f * acc.y + dv * c.y;
    }
    ((float2*)Gout)[selfoff] = o;
}

// ---------------- launch --------------------------------------------------------
extern "C" void kernel_launch(void* const* d_in, const int* in_sizes, int n_in,
                              void* d_out, int out_size) {
    const float* x  = (const float*)d_in[0];
    const int*   ei = (const int*)d_in[1];
    int n = in_sizes[0] / DM;
    int E = in_sizes[1] / 2;
    const int* src = ei;
    const int* dst = ei + E;

    const float* W0 = (const float*)d_in[2];
    const float* b0 = (const float*)d_in[3];
    const float* W1 = (const float*)d_in[4];
    const float* b1 = (const float*)d_in[5];
    const float* W2 = (const float*)d_in[6];
    const float* b2 = (const float*)d_in[7];

    void *cnt_p = nullptr, *bv0_p = nullptr, *bv1_p = nullptr;
    void *bufA_p = nullptr, *bufB_p = nullptr;
    cudaGetSymbolAddress(&cnt_p, g_cnt);
    cudaGetSymbolAddress(&bv0_p, g_bv0);
    cudaGetSymbolAddress(&bv1_p, g_bv1);
    cudaGetSymbolAddress(&bufA_p, g_bufA);
    cudaGetSymbolAddress(&bufB_p, g_bufB);

    // one-time side stream + events (created on first call, before graph capture)
    static cudaStream_t s1 = nullptr;
    static cudaEvent_t ev_fork = nullptr, ev_scan = nullptr, ev_side = nullptr;
    if (!s1) {
        cudaStreamCreateWithFlags(&s1, cudaStreamNonBlocking);
        cudaEventCreateWithFlags(&ev_fork, cudaEventDisableTiming);
        cudaEventCreateWithFlags(&ev_scan, cudaEventDisableTiming);
        cudaEventCreateWithFlags(&ev_side, cudaEventDisableTiming);
    }

    int nb = (n + 1023) / 1024;
    int e4 = (E + 3) / 4;

    // main stream: preprocessing chain
    cudaMemsetAsync(cnt_p, 0, (size_t)(2 * MAXN + 4) * sizeof(int));
    cudaEventRecord(ev_fork, 0);

    // side stream: wfuse immediately (independent of edges)
    cudaStreamWaitEvent(s1, ev_fork, 0);
    k_wfuse<<<1, 256, 0, s1>>>(W0, b0, W1, b1, W2);

    k_count<<<(e4 + 255) / 256, 256>>>(dst, E);
    k_scanf<<<nb, 256>>>(n, nb);
    cudaEventRecord(ev_scan, 0);

    // side stream: gemm after dis (scanf) is ready; overlaps with fill
    cudaStreamWaitEvent(s1, ev_scan, 0);
    int gemm_blocks = (n + 63) / 64;
    k_gemm<<<gemm_blocks, 256, 0, s1>>>(x, n);
    cudaEventRecord(ev_side, s1);

    k_fill<<<(e4 + 255) / 256, 256>>>(src, dst, E);
    cudaStreamWaitEvent(0, ev_side, 0);   // join before aggregation

    int agg_blocks = (n + 7) / 8;
    k_agg<<<agg_blocks, 256>>>((const float*)bufA_p, (const float*)bv0_p, (float*)bufB_p, n, 0);
    k_agg<<<agg_blocks, 256>>>((const float*)bufB_p, (const float*)bv1_p, (float*)bufA_p, n, 0);
    k_agg<<<agg_blocks, 256>>>((const float*)bufA_p, b2, (float*)d_out, n, 1);
}